// round 1
// baseline (speedup 1.0000x reference)
#include <cuda_runtime.h>
#include <cuda_bf16.h>

#define T_STEPS 4096
#define BATCH   256
#define IN_DIM  2
#define HID     32
#define G3      96   // 3 * HID gate rows

// Scratch (device globals — no allocation allowed).
// g_xg padded by 2 steps for the software-pipelined prefetch.
__device__ float g_xg[(T_STEPS + 2) * G3];
__device__ float g_hs[T_STEPS * HID];

// ---------------------------------------------------------------------------
// Kernel 1: xg[t,g] = b_ih[g] + w_ih[g,:] . x[t, 255, :]   (I = 2)
// ---------------------------------------------------------------------------
__global__ void precompute_xg(const float* __restrict__ x,
                              const float* __restrict__ w_ih,
                              const float* __restrict__ b_ih) {
    int idx = blockIdx.x * blockDim.x + threadIdx.x;
    if (idx >= T_STEPS * G3) return;
    int t = idx / G3;
    int g = idx - t * G3;
    // x layout (T, B, I): batch 255 -> offsets 510, 511 within each t-slab of 512
    float x0 = __ldg(&x[t * (BATCH * IN_DIM) + (BATCH - 1) * IN_DIM + 0]);
    float x1 = __ldg(&x[t * (BATCH * IN_DIM) + (BATCH - 1) * IN_DIM + 1]);
    g_xg[idx] = b_ih[g] + w_ih[g * 2 + 0] * x0 + w_ih[g * 2 + 1] * x1;
}

// ---------------------------------------------------------------------------
// Fast activations (EX2/RCP MUFU based; ~1e-7 rel err, no NaN at extremes)
// ---------------------------------------------------------------------------
__device__ __forceinline__ float fast_sigmoid(float x) {
    // 1/(1+e^{-x}); e^{-x}->inf => rcp(inf)=0 OK
    return __frcp_rn(1.0f + __expf(-x));
}
__device__ __forceinline__ float fast_tanh(float x) {
    // 1 - 2/(e^{2x}+1); e->inf => 1, e->0 => -1 (no inf/inf NaN)
    float e = __expf(2.0f * x);
    return 1.0f - __fdividef(2.0f, e + 1.0f);
}

// ---------------------------------------------------------------------------
// Kernel 2: the sequential GRU chain. 1 block, 96 threads (one per gate row).
// ---------------------------------------------------------------------------
__global__ void __launch_bounds__(G3, 1)
gru_seq(const float* __restrict__ w_hh, const float* __restrict__ b_hh) {
    __shared__ float h_sh[HID];
    __shared__ float hg_sh[G3];
    __shared__ float xn_sh[HID];

    const int g = threadIdx.x;

    // Each thread owns one row of w_hh in registers.
    float w[HID];
#pragma unroll
    for (int k = 0; k < HID; k++) w[k] = w_hh[g * HID + k];
    const float bh = b_hh[g];

    if (g < HID) h_sh[g] = 0.0f;
    float h_old = 0.0f;

    // Software-pipelined xg prefetch (depth 2) to keep global latency off the
    // critical path.
    float xv  = g_xg[g];
    float xv1 = g_xg[G3 + g];
    __syncthreads();

    for (int t = 0; t < T_STEPS; t++) {
        float xv2 = g_xg[(t + 2) * G3 + g];   // prefetch t+2 (buffer padded)

        // hg[g] = b_hh[g] + w_hh[g,:] . h   (broadcast smem reads, 4 accums)
        float a0 = 0.0f, a1 = 0.0f, a2 = 0.0f, a3 = 0.0f;
#pragma unroll
        for (int k = 0; k < HID; k += 4) {
            a0 += w[k + 0] * h_sh[k + 0];
            a1 += w[k + 1] * h_sh[k + 1];
            a2 += w[k + 2] * h_sh[k + 2];
            a3 += w[k + 3] * h_sh[k + 3];
        }
        float acc = bh + ((a0 + a1) + (a2 + a3));

        if (g < 2 * HID) {
            hg_sh[g] = acc + xv;          // fold xr/xz in directly
        } else {
            hg_sh[g] = acc;               // hn stays pure (needed for r*hn)
            xn_sh[g - 2 * HID] = xv;      // pass xn via smem
        }
        __syncthreads();

        if (g < HID) {
            float r = fast_sigmoid(hg_sh[g]);
            float z = fast_sigmoid(hg_sh[HID + g]);
            float n = fast_tanh(xn_sh[g] + r * hg_sh[2 * HID + g]);
            float h = n + z * (h_old - n);   // (1-z)*n + z*h
            h_sh[g] = h;
            g_hs[t * HID + g] = h;           // fire-and-forget store
            h_old = h;
        }
        __syncthreads();

        xv = xv1;
        xv1 = xv2;
    }
}

// ---------------------------------------------------------------------------
// Kernel 3: out[t] = b_fc + w_fc . h_t   (warp per timestep, shfl reduce)
// ---------------------------------------------------------------------------
__global__ void fc_kernel(const float* __restrict__ w_fc,
                          const float* __restrict__ b_fc,
                          float* __restrict__ out) {
    int t = blockIdx.x;
    int j = threadIdx.x;
    float v = w_fc[j] * g_hs[t * HID + j];
#pragma unroll
    for (int off = 16; off > 0; off >>= 1)
        v += __shfl_xor_sync(0xFFFFFFFFu, v, off);
    if (j == 0) out[t] = v + b_fc[0];
}

// ---------------------------------------------------------------------------
extern "C" void kernel_launch(void* const* d_in, const int* in_sizes, int n_in,
                              void* d_out, int out_size) {
    const float* x    = (const float*)d_in[0];
    const float* w_ih = (const float*)d_in[1];
    const float* w_hh = (const float*)d_in[2];
    const float* b_ih = (const float*)d_in[3];
    const float* b_hh = (const float*)d_in[4];
    const float* w_fc = (const float*)d_in[5];
    const float* b_fc = (const float*)d_in[6];
    float* out = (float*)d_out;

    precompute_xg<<<(T_STEPS * G3 + 255) / 256, 256>>>(x, w_ih, b_ih);
    gru_seq<<<1, G3>>>(w_hh, b_hh);
    fc_kernel<<<T_STEPS, HID>>>(w_fc, b_fc, out);
}

// round 2
// speedup vs baseline: 1.1537x; 1.1537x over previous
#include <cuda_runtime.h>
#include <cuda_bf16.h>

#define T_STEPS 4096
#define BATCH   256
#define HID     32
#define G3      96

// Scratch (device globals). Padded by 2 steps for the depth-2 prefetch.
__device__ float g_xg_rz[(T_STEPS + 2) * 2 * HID];   // [t][j] -> (xr+br, xz+bz) interleaved
__device__ float g_xg_n [(T_STEPS + 2) * HID];       // [t][j] -> xn (b_ih only)
__device__ float g_hs   [T_STEPS * HID];

// ---------------------------------------------------------------------------
// f32x2 packed helpers (sm_100+; ptxas never emits FFMA2 from C++)
// ---------------------------------------------------------------------------
__device__ __forceinline__ unsigned long long ffma2(unsigned long long a,
                                                    unsigned long long b,
                                                    unsigned long long c) {
    unsigned long long d;
    asm("fma.rn.f32x2 %0, %1, %2, %3;" : "=l"(d) : "l"(a), "l"(b), "l"(c));
    return d;
}
__device__ __forceinline__ unsigned long long pack2(float lo, float hi) {
    unsigned long long d;
    asm("mov.b64 %0, {%1, %2};"
        : "=l"(d) : "r"(__float_as_uint(lo)), "r"(__float_as_uint(hi)));
    return d;
}
__device__ __forceinline__ float f32x2_sum(unsigned long long a) {
    unsigned int lo, hi;
    asm("mov.b64 {%0, %1}, %2;" : "=r"(lo), "=r"(hi) : "l"(a));
    return __uint_as_float(lo) + __uint_as_float(hi);
}
__device__ __forceinline__ void unpack2(unsigned long long a, float& lo, float& hi) {
    unsigned int l, h;
    asm("mov.b64 {%0, %1}, %2;" : "=r"(l), "=r"(h) : "l"(a));
    lo = __uint_as_float(l); hi = __uint_as_float(h);
}
__device__ __forceinline__ float tanh_a(float x) {
    float y;
    asm("tanh.approx.f32 %0, %1;" : "=f"(y) : "f"(x));
    return y;
}
__device__ __forceinline__ float sigmoid_t(float x) {
    // sigmoid(x) = 0.5 + 0.5*tanh(x/2) : FMUL + MUFU.TANH + FFMA
    return fmaf(tanh_a(0.5f * x), 0.5f, 0.5f);
}

// ---------------------------------------------------------------------------
// Kernel 1: xg precompute for batch row 255 (the only one that matters).
// r,z rows get b_hh folded in; n row keeps only b_ih (b_hh[n] must stay
// inside hn because of the r*hn product).
// ---------------------------------------------------------------------------
__global__ void precompute_xg(const float* __restrict__ x,
                              const float* __restrict__ w_ih,
                              const float* __restrict__ b_ih,
                              const float* __restrict__ b_hh) {
    int idx = blockIdx.x * blockDim.x + threadIdx.x;
    if (idx >= T_STEPS * G3) return;
    int t = idx / G3;
    int g = idx - t * G3;
    float x0 = __ldg(&x[t * (BATCH * 2) + (BATCH - 1) * 2 + 0]);
    float x1 = __ldg(&x[t * (BATCH * 2) + (BATCH - 1) * 2 + 1]);
    float v = b_ih[g] + w_ih[g * 2 + 0] * x0 + w_ih[g * 2 + 1] * x1;
    if (g < HID) {
        g_xg_rz[t * 2 * HID + 2 * g + 0] = v + b_hh[g];
    } else if (g < 2 * HID) {
        g_xg_rz[t * 2 * HID + 2 * (g - HID) + 1] = v + b_hh[g];
    } else {
        g_xg_n[t * HID + (g - 2 * HID)] = v;
    }
}

// ---------------------------------------------------------------------------
// Kernel 2: sequential GRU, ONE warp. Lane j owns hidden unit j and gate
// rows j, 32+j, 64+j (96 weights = 48 packed f32x2 pairs in registers).
// ---------------------------------------------------------------------------
__global__ void __launch_bounds__(32, 1)
gru_seq(const float* __restrict__ w_hh, const float* __restrict__ b_hh) {
    __shared__ __align__(16) float h_sh[HID];

    const int j = threadIdx.x;

    // Weight rows as packed (w[2p], w[2p+1]) pairs; rows are 128B so the
    // natural layout is already pair-aligned.
    unsigned long long wr[16], wz[16], wn[16];
    const unsigned long long* W = (const unsigned long long*)w_hh;
#pragma unroll
    for (int p = 0; p < 16; p++) {
        wr[p] = W[(0 * HID + j) * 16 + p];
        wz[p] = W[(1 * HID + j) * 16 + p];
        wn[p] = W[(2 * HID + j) * 16 + p];
    }
    const unsigned long long bn_pack = pack2(b_hh[2 * HID + j], 0.0f);

    h_sh[j] = 0.0f;
    float h_old = 0.0f;

    const unsigned long long* xrz = (const unsigned long long*)g_xg_rz;
    const float*              xnp = g_xg_n;

    // Depth-2 software pipeline on the xg stream (covers ~262 cyc L2 hit).
    unsigned long long c_rz  = xrz[0 * HID + j];
    unsigned long long n1_rz = xrz[1 * HID + j];
    float              c_n   = xnp[0 * HID + j];
    float              n1_n  = xnp[1 * HID + j];
    __syncwarp();

#pragma unroll 2
    for (int t = 0; t < T_STEPS; t++) {
        unsigned long long n2_rz = xrz[(t + 2) * HID + j];
        float              n2_n  = xnp[(t + 2) * HID + j];

        float xr, xz;
        unpack2(c_rz, xr, xz);
        unsigned long long ar = pack2(xr, 0.0f);
        unsigned long long az = pack2(xz, 0.0f);
        unsigned long long an = bn_pack;

        // hg = W . h : broadcast LDS.128, 48 FFMA2 (the issue-bound core).
        const ulonglong2* hp = (const ulonglong2*)h_sh;
#pragma unroll
        for (int i = 0; i < 8; i++) {
            ulonglong2 hq = hp[i];
            ar = ffma2(wr[2 * i + 0], hq.x, ar);
            az = ffma2(wz[2 * i + 0], hq.x, az);
            an = ffma2(wn[2 * i + 0], hq.x, an);
            ar = ffma2(wr[2 * i + 1], hq.y, ar);
            az = ffma2(wz[2 * i + 1], hq.y, az);
            an = ffma2(wn[2 * i + 1], hq.y, an);
        }
        float pre_r = f32x2_sum(ar);   // includes xr + br + bhr
        float pre_z = f32x2_sum(az);
        float hn    = f32x2_sum(an);   // Wn.h + bn

        float r = sigmoid_t(pre_r);
        float z = sigmoid_t(pre_z);
        float n = tanh_a(fmaf(r, hn, c_n));
        float h = fmaf(z, h_old - n, n);     // (1-z)*n + z*h

        g_hs[t * HID + j] = h;               // fire-and-forget, coalesced
        h_old = h;
        h_sh[j] = h;                         // no WAR: converged warp passed all LDS
        __syncwarp();                        // RAW visibility for next step

        c_rz = n1_rz; n1_rz = n2_rz;
        c_n  = n1_n;  n1_n  = n2_n;
    }
}

// ---------------------------------------------------------------------------
// Kernel 3: out[t] = b_fc + w_fc . h_t  (warp per timestep)
// ---------------------------------------------------------------------------
__global__ void fc_kernel(const float* __restrict__ w_fc,
                          const float* __restrict__ b_fc,
                          float* __restrict__ out) {
    int t = blockIdx.x;
    int j = threadIdx.x;
    float v = w_fc[j] * g_hs[t * HID + j];
#pragma unroll
    for (int off = 16; off > 0; off >>= 1)
        v += __shfl_xor_sync(0xFFFFFFFFu, v, off);
    if (j == 0) out[t] = v + b_fc[0];
}

// ---------------------------------------------------------------------------
extern "C" void kernel_launch(void* const* d_in, const int* in_sizes, int n_in,
                              void* d_out, int out_size) {
    const float* x    = (const float*)d_in[0];
    const float* w_ih = (const float*)d_in[1];
    const float* w_hh = (const float*)d_in[2];
    const float* b_ih = (const float*)d_in[3];
    const float* b_hh = (const float*)d_in[4];
    const float* w_fc = (const float*)d_in[5];
    const float* b_fc = (const float*)d_in[6];
    float* out = (float*)d_out;

    precompute_xg<<<(T_STEPS * G3 + 255) / 256, 256>>>(x, w_ih, b_ih, b_hh);
    gru_seq<<<1, 32>>>(w_hh, b_hh);
    fc_kernel<<<T_STEPS, HID>>>(w_fc, b_fc, out);
}

// round 3
// speedup vs baseline: 1.8049x; 1.5644x over previous
#include <cuda_runtime.h>
#include <cuda_bf16.h>

#define T_STEPS 4096
#define BATCH   256
#define HID     32
#define G3      96

// Scratch (device globals). g_xg layout: [t][gate][j], biases folded for r,z.
// Padded 2 steps for the depth-2 prefetch.
__device__ float g_xg[(T_STEPS + 2) * G3];
__device__ float g_hs[T_STEPS * HID];

// ---------------------------------------------------------------------------
// f32x2 helpers (sm_100+)
// ---------------------------------------------------------------------------
__device__ __forceinline__ unsigned long long ffma2(unsigned long long a,
                                                    unsigned long long b,
                                                    unsigned long long c) {
    unsigned long long d;
    asm("fma.rn.f32x2 %0, %1, %2, %3;" : "=l"(d) : "l"(a), "l"(b), "l"(c));
    return d;
}
__device__ __forceinline__ unsigned long long pack2(float lo, float hi) {
    unsigned long long d;
    asm("mov.b64 %0, {%1, %2};"
        : "=l"(d) : "r"(__float_as_uint(lo)), "r"(__float_as_uint(hi)));
    return d;
}
__device__ __forceinline__ float f32x2_sum(unsigned long long a) {
    unsigned int lo, hi;
    asm("mov.b64 {%0, %1}, %2;" : "=r"(lo), "=r"(hi) : "l"(a));
    return __uint_as_float(lo) + __uint_as_float(hi);
}
__device__ __forceinline__ float tanh_a(float x) {
    float y;
    asm("tanh.approx.f32 %0, %1;" : "=f"(y) : "f"(x));
    return y;
}
__device__ __forceinline__ float sigmoid_t(float x) {
    return fmaf(tanh_a(0.5f * x), 0.5f, 0.5f);   // FMUL + MUFU.TANH + FFMA
}

// ---------------------------------------------------------------------------
// Kernel 1: xg precompute for batch row 255.
// r,z rows: + b_ih + b_hh (fully folded). n row: + b_ih only (b_hh_n must
// stay inside hn because of the r*hn product).
// ---------------------------------------------------------------------------
__global__ void precompute_xg(const float* __restrict__ x,
                              const float* __restrict__ w_ih,
                              const float* __restrict__ b_ih,
                              const float* __restrict__ b_hh) {
    int idx = blockIdx.x * blockDim.x + threadIdx.x;
    if (idx >= T_STEPS * G3) return;
    int t = idx / G3;
    int g = idx - t * G3;
    float x0 = __ldg(&x[t * (BATCH * 2) + (BATCH - 1) * 2 + 0]);
    float x1 = __ldg(&x[t * (BATCH * 2) + (BATCH - 1) * 2 + 1]);
    float v = b_ih[g] + w_ih[g * 2 + 0] * x0 + w_ih[g * 2 + 1] * x1;
    if (g < 2 * HID) v += b_hh[g];           // fold recurrent bias for r,z
    g_xg[t * G3 + g] = v;                    // layout [t][gate][j]
}

// ---------------------------------------------------------------------------
// Kernel 2: sequential GRU. 3 warps, warp g owns gate g (32 rows, one per
// lane). W0 = r (finisher), W1 = z, W2 = n (raw hn; also stages xn).
// ---------------------------------------------------------------------------
__global__ void __launch_bounds__(G3, 1)
gru_seq(const float* __restrict__ w_hh, const float* __restrict__ b_hh) {
    __shared__ __align__(16) float h_sh[HID];
    __shared__ __align__(16) float sh_g[HID * 4];   // per j: (z, hn, xn, pad)

    const int w = threadIdx.x >> 5;      // warp = gate
    const int j = threadIdx.x & 31;      // lane = hidden unit / row within gate

    // 16 packed weight pairs per thread (row w*32+j of w_hh, 128B-aligned).
    unsigned long long wk[16];
    const unsigned long long* W = (const unsigned long long*)w_hh;
#pragma unroll
    for (int p = 0; p < 16; p++) wk[p] = W[(w * HID + j) * 16 + p];

    const float bn = (w == 2) ? b_hh[2 * HID + j] : 0.0f;

    if (threadIdx.x < HID) h_sh[threadIdx.x] = 0.0f;
    float h_old = 0.0f;

    // Depth-2 prefetch: each warp streams its own gate column of g_xg.
    const float* xs = g_xg + w * HID + j;
    float xc = xs[0 * G3];
    float x1 = xs[1 * G3];
    __syncthreads();

#pragma unroll 2
    for (int t = 0; t < T_STEPS; t++) {
        float x2 = xs[(t + 2) * G3];     // prefetch t+2 (padded buffer)

        // pre = (xr|xz|bn) + W_gate[row j] . h   (16 FFMA2, LDS.128 broadcast)
        unsigned long long acc = pack2((w == 2) ? bn : xc, 0.0f);
        const ulonglong2* hp = (const ulonglong2*)h_sh;
#pragma unroll
        for (int i = 0; i < 4; i++) {
            ulonglong2 hq = hp[i];
            acc = ffma2(wk[2 * i + 0], hq.x, acc);
            acc = ffma2(wk[2 * i + 1], hq.y, acc);
        }
#pragma unroll
        for (int i = 4; i < 8; i++) {
            ulonglong2 hq = hp[i];
            acc = ffma2(wk[2 * i + 0], hq.x, acc);
            acc = ffma2(wk[2 * i + 1], hq.y, acc);
        }
        float pre = f32x2_sum(acc);

        float r = 0.0f;
        if (w == 0) {
            r = sigmoid_t(pre);                  // finisher keeps r local
        } else if (w == 1) {
            sh_g[4 * j + 0] = sigmoid_t(pre);    // z
        } else {
            sh_g[4 * j + 1] = pre;               // raw hn (incl bn)
            sh_g[4 * j + 2] = xc;                // stage xn for the finisher
        }
        __syncthreads();                         // hop 1: gates -> finisher

        if (w == 0) {
            float4 q = ((const float4*)sh_g)[j]; // (z, hn, xn, pad)
            float n = tanh_a(fmaf(r, q.y, q.z));
            float h = fmaf(q.x, h_old - n, n);   // (1-z)*n + z*h_old
            h_sh[j] = h;
            g_hs[t * HID + j] = h;               // fire-and-forget, coalesced
            h_old = h;
        }
        __syncthreads();                         // hop 2: h -> all warps

        xc = x1; x1 = x2;
    }
}

// ---------------------------------------------------------------------------
// Kernel 3: out[t] = b_fc + w_fc . h_t  (warp per timestep)
// ---------------------------------------------------------------------------
__global__ void fc_kernel(const float* __restrict__ w_fc,
                          const float* __restrict__ b_fc,
                          float* __restrict__ out) {
    int t = blockIdx.x;
    int j = threadIdx.x;
    float v = w_fc[j] * g_hs[t * HID + j];
#pragma unroll
    for (int off = 16; off > 0; off >>= 1)
        v += __shfl_xor_sync(0xFFFFFFFFu, v, off);
    if (j == 0) out[t] = v + b_fc[0];
}

// ---------------------------------------------------------------------------
extern "C" void kernel_launch(void* const* d_in, const int* in_sizes, int n_in,
                              void* d_out, int out_size) {
    const float* x    = (const float*)d_in[0];
    const float* w_ih = (const float*)d_in[1];
    const float* w_hh = (const float*)d_in[2];
    const float* b_ih = (const float*)d_in[3];
    const float* b_hh = (const float*)d_in[4];
    const float* w_fc = (const float*)d_in[5];
    const float* b_fc = (const float*)d_in[6];
    float* out = (float*)d_out;

    precompute_xg<<<(T_STEPS * G3 + 255) / 256, 256>>>(x, w_ih, b_ih, b_hh);
    gru_seq<<<1, G3>>>(w_hh, b_hh);
    fc_kernel<<<T_STEPS, HID>>>(w_fc, b_fc, out);
}

// round 4
// speedup vs baseline: 1.8587x; 1.0299x over previous
#include <cuda_runtime.h>
#include <cuda_bf16.h>

#define T_STEPS 4096
#define BATCH   256
#define HID     32
#define G3      96

// Scratch (device globals). g_xg layout: [t][gate][j], biases folded for r,z.
// Padded 2 steps for the depth-2 prefetch.
__device__ float g_xg[(T_STEPS + 2) * G3];
__device__ float g_hs[T_STEPS * HID];

// ---------------------------------------------------------------------------
// f32x2 helpers (sm_100+)
// ---------------------------------------------------------------------------
__device__ __forceinline__ unsigned long long ffma2(unsigned long long a,
                                                    unsigned long long b,
                                                    unsigned long long c) {
    unsigned long long d;
    asm("fma.rn.f32x2 %0, %1, %2, %3;" : "=l"(d) : "l"(a), "l"(b), "l"(c));
    return d;
}
__device__ __forceinline__ unsigned long long pack2(float lo, float hi) {
    unsigned long long d;
    asm("mov.b64 %0, {%1, %2};"
        : "=l"(d) : "r"(__float_as_uint(lo)), "r"(__float_as_uint(hi)));
    return d;
}
__device__ __forceinline__ float f32x2_sum2(unsigned long long a,
                                            unsigned long long b) {
    unsigned int al, ah, bl, bh;
    asm("mov.b64 {%0, %1}, %2;" : "=r"(al), "=r"(ah) : "l"(a));
    asm("mov.b64 {%0, %1}, %2;" : "=r"(bl), "=r"(bh) : "l"(b));
    return (__uint_as_float(al) + __uint_as_float(ah)) +
           (__uint_as_float(bl) + __uint_as_float(bh));
}
__device__ __forceinline__ float tanh_a(float x) {
    float y;
    asm("tanh.approx.f32 %0, %1;" : "=f"(y) : "f"(x));
    return y;
}
__device__ __forceinline__ float sigmoid_t(float x) {
    return fmaf(tanh_a(0.5f * x), 0.5f, 0.5f);   // FMUL + MUFU.TANH + FFMA
}

// ---------------------------------------------------------------------------
// Kernel 1: xg precompute for batch row 255.
// r,z rows: + b_ih + b_hh folded. n row: + b_ih only (b_hh_n stays inside hn
// because of the r*hn product).
// ---------------------------------------------------------------------------
__global__ void precompute_xg(const float* __restrict__ x,
                              const float* __restrict__ w_ih,
                              const float* __restrict__ b_ih,
                              const float* __restrict__ b_hh) {
    int idx = blockIdx.x * blockDim.x + threadIdx.x;
    if (idx >= T_STEPS * G3) return;
    int t = idx / G3;
    int g = idx - t * G3;
    float x0 = __ldg(&x[t * (BATCH * 2) + (BATCH - 1) * 2 + 0]);
    float x1 = __ldg(&x[t * (BATCH * 2) + (BATCH - 1) * 2 + 1]);
    float v = b_ih[g] + w_ih[g * 2 + 0] * x0 + w_ih[g * 2 + 1] * x1;
    if (g < 2 * HID) v += b_hh[g];
    g_xg[t * G3 + g] = v;                    // layout [t][gate][j]
}

// ---------------------------------------------------------------------------
// Kernel 2: sequential GRU. 3 warps, warp g owns gate g's 32 rows (one per
// lane). ONE __syncthreads per step; finisher computed redundantly by every
// warp (identical FMAs -> bitwise-identical h), each warp keeping a private
// h copy closed by __syncwarp. Gate staging double-buffered on t&1 to avoid
// the WAR race the single barrier would otherwise create.
// ---------------------------------------------------------------------------
__global__ void __launch_bounds__(G3, 1)
gru_seq(const float* __restrict__ w_hh, const float* __restrict__ b_hh) {
    __shared__ __align__(16) float h_priv[3][HID];      // per-warp h copy
    __shared__ float sh_r [2][HID];                     // double-buffered gates
    __shared__ float sh_z [2][HID];
    __shared__ float sh_hn[2][HID];
    __shared__ float sh_xn[2][HID];

    const int w = threadIdx.x >> 5;      // warp = gate (0:r, 1:z, 2:n)
    const int j = threadIdx.x & 31;      // lane = hidden unit / row

    // 16 packed weight pairs (row w*32+j of w_hh; rows are 128B-aligned).
    unsigned long long wk[16];
    const unsigned long long* W = (const unsigned long long*)w_hh;
#pragma unroll
    for (int p = 0; p < 16; p++) wk[p] = W[(w * HID + j) * 16 + p];

    const float bn = b_hh[2 * HID + j];  // only used by w==2

    h_priv[w][j] = 0.0f;
    float h_old = 0.0f;

    // Depth-2 prefetch of this warp's gate column.
    const float* xs = g_xg + w * HID + j;
    float xc = xs[0 * G3];
    float x1 = xs[1 * G3];
    __syncthreads();

#pragma unroll 2
    for (int t = 0; t < T_STEPS; t++) {
        const int p = t & 1;
        float x2 = xs[(t + 2) * G3];               // prefetch t+2

        // ---- Phase A: pre = init + W_row . h  (2 accumulators) ----
        unsigned long long a0 = pack2((w == 2) ? bn : xc, 0.0f);
        unsigned long long a1 = pack2(0.0f, 0.0f);
        const ulonglong2* hp = (const ulonglong2*)h_priv[w];
#pragma unroll
        for (int i = 0; i < 8; i++) {
            ulonglong2 hq = hp[i];
            a0 = ffma2(wk[2 * i + 0], hq.x, a0);
            a1 = ffma2(wk[2 * i + 1], hq.y, a1);
        }
        float pre = f32x2_sum2(a0, a1);

        if (w == 0)      sh_r [p][j] = sigmoid_t(pre);
        else if (w == 1) sh_z [p][j] = sigmoid_t(pre);
        else             { sh_hn[p][j] = pre; sh_xn[p][j] = xc; }
        __syncthreads();                           // the ONE block barrier

        // ---- Phase B: every warp redundantly finishes h ----
        float r  = sh_r [p][j];
        float z  = sh_z [p][j];
        float hn = sh_hn[p][j];
        float xn = sh_xn[p][j];
        float n = tanh_a(fmaf(r, hn, xn));
        float h = fmaf(z, h_old - n, n);           // (1-z)*n + z*h_old
        h_old = h;
        h_priv[w][j] = h;                          // private copy
        if (w == 0) g_hs[t * HID + j] = h;         // fire-and-forget
        __syncwarp();                              // intra-warp h visibility

        xc = x1; x1 = x2;
    }
}

// ---------------------------------------------------------------------------
// Kernel 3: out[t] = b_fc + w_fc . h_t  (warp per timestep)
// ---------------------------------------------------------------------------
__global__ void fc_kernel(const float* __restrict__ w_fc,
                          const float* __restrict__ b_fc,
                          float* __restrict__ out) {
    int t = blockIdx.x;
    int j = threadIdx.x;
    float v = w_fc[j] * g_hs[t * HID + j];
#pragma unroll
    for (int off = 16; off > 0; off >>= 1)
        v += __shfl_xor_sync(0xFFFFFFFFu, v, off);
    if (j == 0) out[t] = v + b_fc[0];
}

// ---------------------------------------------------------------------------
extern "C" void kernel_launch(void* const* d_in, const int* in_sizes, int n_in,
                              void* d_out, int out_size) {
    const float* x    = (const float*)d_in[0];
    const float* w_ih = (const float*)d_in[1];
    const float* w_hh = (const float*)d_in[2];
    const float* b_ih = (const float*)d_in[3];
    const float* b_hh = (const float*)d_in[4];
    const float* w_fc = (const float*)d_in[5];
    const float* b_fc = (const float*)d_in[6];
    float* out = (float*)d_out;

    precompute_xg<<<(T_STEPS * G3 + 255) / 256, 256>>>(x, w_ih, b_ih, b_hh);
    gru_seq<<<1, G3>>>(w_hh, b_hh);
    fc_kernel<<<T_STEPS, HID>>>(w_fc, b_fc, out);
}